// round 12
// baseline (speedup 1.0000x reference)
#include <cuda_runtime.h>
#include <cuda_bf16.h>

// GCN 3-layer, N=100000, E=800000. Aggregate in the smaller dim per layer.
// R10: tf32 MMA GEMM with 3xTF32 error compensation (hi/lo split of both
//      operands, 3 MMAs per tile into one fp32 accumulator). R9's plain tf32
//      landed at rel_err 1.4e-3 (>1e-3); 3xTF32 recovers ~fp32 precision
//      while the tensor-pipe cost stays negligible. 211KB smem, 1 block/SM.

static constexpr int N = 100000;
static constexpr int E = 800000;

static constexpr int TBN = 128;          // nodes per block
static constexpr int H1_STRIDE = 132;    // conflict-free A-frag loads
static constexpr int W2_STRIDE = 72;     // conflict-free B-frag loads
static constexpr int SM_H1 = TBN * H1_STRIDE;          // 16896 floats
static constexpr int SM_W2 = 128 * W2_STRIDE;          // 9216 floats
// hi + lo tiles for both operands, then W1 + b1
static constexpr int SMEM_FLOATS = 2 * SM_H1 + 2 * SM_W2 + 512 + 128;
static constexpr int SMEM_BYTES = SMEM_FLOATS * 4;     // 211,456 bytes

__device__ float4 g_agg1[N];        // [N,4]
__device__ float4 g_t2[N * 16];     // [N,64]
__device__ float4 g_agg2[N * 16];   // [N,64]
__device__ float  g_t3[N];
__device__ float  g_deg[N];
__device__ float  g_norm[E];
__device__ int    g_src[E];
__device__ int    g_dst[E];
__device__ int    g_is64;

__device__ __forceinline__ void red_add_v4(float* p, float4 v) {
    asm volatile("red.global.add.v4.f32 [%0], {%1,%2,%3,%4};"
                 :: "l"(p), "f"(v.x), "f"(v.y), "f"(v.z), "f"(v.w)
                 : "memory");
}
__device__ __forceinline__ float to_tf32(float v) {
    float r;
    asm("cvt.rna.tf32.f32 %0, %1;" : "=f"(r) : "f"(v));
    return r;
}
__device__ __forceinline__ void mma_tf32(
    float& c0, float& c1, float& c2, float& c3,
    unsigned a0, unsigned a1, unsigned a2, unsigned a3,
    unsigned b0, unsigned b1) {
    asm("mma.sync.aligned.m16n8k8.row.col.f32.tf32.tf32.f32 "
        "{%0,%1,%2,%3}, {%4,%5,%6,%7}, {%8,%9}, {%0,%1,%2,%3};"
        : "+f"(c0), "+f"(c1), "+f"(c2), "+f"(c3)
        : "r"(a0), "r"(a1), "r"(a2), "r"(a3), "r"(b0), "r"(b1));
}

// ---------------- kernels ----------------

// grid-wide: init deg=1 (self-loop) and agg1=0; block 0 sniffs edge dtype.
__global__ void k_detect_init(const int* __restrict__ ei32) {
    int i = blockIdx.x * blockDim.x + threadIdx.x;
    int stride = gridDim.x * blockDim.x;
    const float4 z4 = make_float4(0.f, 0.f, 0.f, 0.f);
    for (int j = i; j < N; j += stride) {
        g_deg[j] = 1.0f;
        g_agg1[j] = z4;
    }
    if (blockIdx.x == 0) {
        __shared__ unsigned s[256];
        unsigned acc = 0;
        for (int t = threadIdx.x; t < 8192; t += 256) acc |= (unsigned)ei32[2 * t + 1];
        s[threadIdx.x] = acc;
        __syncthreads();
        for (int o = 128; o; o >>= 1) {
            if (threadIdx.x < o) s[threadIdx.x] |= s[threadIdx.x + o];
            __syncthreads();
        }
        if (threadIdx.x == 0) g_is64 = (s[0] == 0) ? 1 : 0;
    }
}

__global__ void k_decode_deg(const int* __restrict__ ei32, const float* __restrict__ w) {
    int e = blockIdx.x * blockDim.x + threadIdx.x;
    if (e >= E) return;
    int s, d;
    if (g_is64) { s = ei32[2 * e]; d = ei32[2 * (E + e)]; }
    else        { s = ei32[e];     d = ei32[E + e]; }
    if ((unsigned)s >= (unsigned)N) s = 0;
    if ((unsigned)d >= (unsigned)N) d = 0;
    g_src[e] = s;
    g_dst[e] = d;
    atomicAdd(&g_deg[d], w[e]);
}

__global__ void k_norm_agg1(const float* __restrict__ x, const float* __restrict__ w) {
    int e = blockIdx.x * blockDim.x + threadIdx.x;
    if (e >= E) return;
    int s = g_src[e], d = g_dst[e];
    float nr = rsqrtf(g_deg[s]) * w[e] * rsqrtf(g_deg[d]);
    g_norm[e] = nr;
    float4 v = ((const float4*)x)[s];
    v.x *= nr; v.y *= nr; v.z *= nr; v.w *= nr;
    red_add_v4((float*)&g_agg1[d], v);
}

// fused l1 + gemm2 via 3xTF32 mma. Block computes h1 tile [128x128] split into
// tf32 hi/lo in smem, W2 likewise; 4 warps do [128x64] = h1 @ W2 with
// 3 MMAs per tile (hi*hi + lo*hi + hi*lo). Also zeroes g_agg2 rows.
__global__ __launch_bounds__(128) void k_l1gemm2(
    const float* __restrict__ x, const float* __restrict__ W1,
    const float* __restrict__ b1, const float* __restrict__ W2) {
    extern __shared__ float smem[];
    float* h1h = smem;                     // [128][132] hi
    float* h1l = h1h + SM_H1;              // [128][132] lo
    float* w2h = h1l + SM_H1;              // [128][72]  hi
    float* w2l = w2h + SM_W2;              // [128][72]  lo
    float* w1s = w2l + SM_W2;              // [4][128]
    float* b1s = w1s + 512;                // [128]

    int t = threadIdx.x;
    for (int i = t; i < 128 * 64; i += 128) {
        int k = i >> 6, n = i & 63;
        float v = W2[i];
        float hi = to_tf32(v);
        w2h[k * W2_STRIDE + n] = hi;
        w2l[k * W2_STRIDE + n] = to_tf32(v - hi);
    }
    for (int i = t; i < 512; i += 128) w1s[i] = W1[i];
    b1s[t] = b1[t];

    int node0 = blockIdx.x * TBN;
    int node = node0 + t;
    bool valid = node < N;

    if (valid) {
        const float4 z4 = make_float4(0.f, 0.f, 0.f, 0.f);
        float4* a2 = &g_agg2[node * 16];
#pragma unroll
        for (int c = 0; c < 16; c++) a2[c] = z4;

        float4 ag = g_agg1[node];
        float4 xv = ((const float4*)x)[node];
        float s2 = 1.0f / g_deg[node];
        float v0 = ag.x + s2 * xv.x;
        float v1 = ag.y + s2 * xv.y;
        float v2 = ag.z + s2 * xv.z;
        float v3 = ag.w + s2 * xv.w;
        float* hh = &h1h[t * H1_STRIDE];
        float* hl = &h1l[t * H1_STRIDE];
#pragma unroll 4
        for (int k4 = 0; k4 < 32; k4++) {
            float4 r0 = ((const float4*)w1s)[k4];
            float4 r1 = ((const float4*)(w1s + 128))[k4];
            float4 r2 = ((const float4*)(w1s + 256))[k4];
            float4 r3 = ((const float4*)(w1s + 384))[k4];
            float4 bb = ((const float4*)b1s)[k4];
            float h0 = fmaxf(bb.x + v0 * r0.x + v1 * r1.x + v2 * r2.x + v3 * r3.x, 0.f);
            float h1v = fmaxf(bb.y + v0 * r0.y + v1 * r1.y + v2 * r2.y + v3 * r3.y, 0.f);
            float h2 = fmaxf(bb.z + v0 * r0.z + v1 * r1.z + v2 * r2.z + v3 * r3.z, 0.f);
            float h3 = fmaxf(bb.w + v0 * r0.w + v1 * r1.w + v2 * r2.w + v3 * r3.w, 0.f);
            float e0 = to_tf32(h0), e1 = to_tf32(h1v), e2 = to_tf32(h2), e3 = to_tf32(h3);
            hh[4 * k4 + 0] = e0; hl[4 * k4 + 0] = to_tf32(h0 - e0);
            hh[4 * k4 + 1] = e1; hl[4 * k4 + 1] = to_tf32(h1v - e1);
            hh[4 * k4 + 2] = e2; hl[4 * k4 + 2] = to_tf32(h2 - e2);
            hh[4 * k4 + 3] = e3; hl[4 * k4 + 3] = to_tf32(h3 - e3);
        }
    } else {
        float* hh = &h1h[t * H1_STRIDE];
        float* hl = &h1l[t * H1_STRIDE];
#pragma unroll 8
        for (int k = 0; k < 128; k++) { hh[k] = 0.f; hl[k] = 0.f; }
    }
    __syncthreads();

    // MMA: warp w handles rows [32w, 32w+32) = 2 m-tiles of 16
    int w = t >> 5, lane = t & 31;
    int gid = lane >> 2, tig = lane & 3;
    int m0 = w * 32;

    float c[2][8][4];
#pragma unroll
    for (int mt = 0; mt < 2; mt++)
#pragma unroll
        for (int nt = 0; nt < 8; nt++)
#pragma unroll
            for (int r = 0; r < 4; r++) c[mt][nt][r] = 0.f;

#pragma unroll 1
    for (int kt = 0; kt < 16; kt++) {
        int k0 = kt * 8;
        unsigned ah[2][4], al[2][4];
#pragma unroll
        for (int mt = 0; mt < 2; mt++) {
            int r0 = m0 + mt * 16 + gid;
            int o00 = r0 * H1_STRIDE + k0 + tig;
            int o10 = (r0 + 8) * H1_STRIDE + k0 + tig;
            ah[mt][0] = __float_as_uint(h1h[o00]);
            ah[mt][1] = __float_as_uint(h1h[o10]);
            ah[mt][2] = __float_as_uint(h1h[o00 + 4]);
            ah[mt][3] = __float_as_uint(h1h[o10 + 4]);
            al[mt][0] = __float_as_uint(h1l[o00]);
            al[mt][1] = __float_as_uint(h1l[o10]);
            al[mt][2] = __float_as_uint(h1l[o00 + 4]);
            al[mt][3] = __float_as_uint(h1l[o10 + 4]);
        }
#pragma unroll
        for (int nt = 0; nt < 8; nt++) {
            int n0 = nt * 8;
            int ob0 = (k0 + tig) * W2_STRIDE + n0 + gid;
            int ob1 = (k0 + tig + 4) * W2_STRIDE + n0 + gid;
            unsigned bh0 = __float_as_uint(w2h[ob0]);
            unsigned bh1 = __float_as_uint(w2h[ob1]);
            unsigned bl0 = __float_as_uint(w2l[ob0]);
            unsigned bl1 = __float_as_uint(w2l[ob1]);
#pragma unroll
            for (int mt = 0; mt < 2; mt++) {
                mma_tf32(c[mt][nt][0], c[mt][nt][1], c[mt][nt][2], c[mt][nt][3],
                         al[mt][0], al[mt][1], al[mt][2], al[mt][3], bh0, bh1);
                mma_tf32(c[mt][nt][0], c[mt][nt][1], c[mt][nt][2], c[mt][nt][3],
                         ah[mt][0], ah[mt][1], ah[mt][2], ah[mt][3], bl0, bl1);
                mma_tf32(c[mt][nt][0], c[mt][nt][1], c[mt][nt][2], c[mt][nt][3],
                         ah[mt][0], ah[mt][1], ah[mt][2], ah[mt][3], bh0, bh1);
            }
        }
    }

    // store C -> g_t2
    float* t2f = (float*)g_t2;
#pragma unroll
    for (int mt = 0; mt < 2; mt++) {
        int r0 = node0 + m0 + mt * 16 + gid;
        int r1 = r0 + 8;
#pragma unroll
        for (int nt = 0; nt < 8; nt++) {
            int col = nt * 8 + tig * 2;
            if (r0 < N)
                *(float2*)(t2f + r0 * 64 + col) = make_float2(c[mt][nt][0], c[mt][nt][1]);
            if (r1 < N)
                *(float2*)(t2f + r1 * 64 + col) = make_float2(c[mt][nt][2], c[mt][nt][3]);
        }
    }
}

// layer-2 aggregation in dim 64: 16 threads (float4 chunks) per edge
__global__ void k_agg2() {
    int idx = blockIdx.x * blockDim.x + threadIdx.x;
    if (idx >= E * 16) return;
    int e = idx >> 4, c = idx & 15;
    int s = g_src[e], d = g_dst[e];
    float nr = g_norm[e];
    float4 v = g_t2[s * 16 + c];
    v.x *= nr; v.y *= nr; v.z *= nr; v.w *= nr;
    red_add_v4((float*)&g_agg2[d * 16 + c], v);
}

// fused: h2 = relu(agg2 + dis2*t2 + b2); t3 = h2 . W3; out = dis2*t3 + b3
__global__ void k_l2gemm3(const float* __restrict__ b2, const float* __restrict__ W3,
                          const float* __restrict__ b3, float* __restrict__ out) {
    __shared__ float sw[64];
    __shared__ float sb2[64];
    if (threadIdx.x < 64) { sw[threadIdx.x] = W3[threadIdx.x]; sb2[threadIdx.x] = b2[threadIdx.x]; }
    __syncthreads();
    int gw = (blockIdx.x * blockDim.x + threadIdx.x) >> 5;
    int lane = threadIdx.x & 31;
    if (gw >= N) return;
    float s2 = 1.0f / g_deg[gw];
    float2 a = ((const float2*)((const float*)g_agg2 + gw * 64))[lane];
    float2 t = ((const float2*)((const float*)g_t2   + gw * 64))[lane];
    float h0 = fmaxf(a.x + s2 * t.x + sb2[2 * lane],     0.f);
    float h1 = fmaxf(a.y + s2 * t.y + sb2[2 * lane + 1], 0.f);
    float p = h0 * sw[2 * lane] + h1 * sw[2 * lane + 1];
#pragma unroll
    for (int off = 16; off; off >>= 1) p += __shfl_down_sync(0xffffffffu, p, off);
    if (lane == 0) {
        g_t3[gw] = p;
        out[gw] = s2 * p + b3[0];   // self-loop + bias; edge atomics add on top
    }
}

// layer-3 aggregation (scalar atomics into out)
__global__ void k_agg3(float* __restrict__ out) {
    int e = blockIdx.x * blockDim.x + threadIdx.x;
    if (e >= E) return;
    atomicAdd(&out[g_dst[e]], g_norm[e] * g_t3[g_src[e]]);
}

// ---------------- launch ----------------
extern "C" void kernel_launch(void* const* d_in, const int* in_sizes, int n_in,
                              void* d_out, int out_size) {
    const float* x  = (const float*)d_in[0];
    const int*   ei = (const int*)d_in[1];      // dtype sniffed on device
    const float* w  = (const float*)d_in[2];
    const float* W1 = (const float*)d_in[3];
    const float* b1 = (const float*)d_in[4];
    const float* W2 = (const float*)d_in[5];
    const float* b2 = (const float*)d_in[6];
    const float* W3 = (const float*)d_in[7];
    const float* b3 = (const float*)d_in[8];
    float* out = (float*)d_out;

    const int B = 256;

    cudaFuncSetAttribute(k_l1gemm2, cudaFuncAttributeMaxDynamicSharedMemorySize, SMEM_BYTES);

    k_detect_init<<<(N + B - 1) / B, B>>>(ei);
    k_decode_deg<<<(E + B - 1) / B, B>>>(ei, w);
    k_norm_agg1<<<(E + B - 1) / B, B>>>(x, w);
    k_l1gemm2<<<(N + TBN - 1) / TBN, 128, SMEM_BYTES>>>(x, W1, b1, W2);
    k_agg2<<<(E * 16 + B - 1) / B, B>>>();
    k_l2gemm3<<<(N * 32 + B - 1) / B, B>>>(b2, W3, b3, out);
    k_agg3<<<(E + B - 1) / B, B>>>(out);
}

// round 16
// speedup vs baseline: 1.0771x; 1.0771x over previous
#include <cuda_runtime.h>
#include <cuda_bf16.h>

// GCN 3-layer, N=100000, E=800000. Aggregate in the smaller dim per layer.
// R15: fix R12-256's race — missing __syncthreads() between smem staging
//      (W1/b1/W2 hi/lo) and the h1 compute that reads them. At 128 threads the
//      race never fired; at 256 threads half the warps read unwritten b1s/w1s
//      (rel_err 1.25). One barrier fixes it; all other structure identical.

static constexpr int N = 100000;
static constexpr int E = 800000;

static constexpr int TBN = 128;          // nodes per block
static constexpr int H1_STRIDE = 132;    // conflict-free A-frag loads
static constexpr int W2_STRIDE = 72;     // conflict-free B-frag loads
static constexpr int SM_H1 = TBN * H1_STRIDE;          // 16896 floats
static constexpr int SM_W2 = 128 * W2_STRIDE;          // 9216 floats
static constexpr int SMEM_FLOATS = 2 * SM_H1 + 2 * SM_W2 + 512 + 128;
static constexpr int SMEM_BYTES = SMEM_FLOATS * 4;     // 211,456 bytes

__device__ float4 g_agg1[N];        // [N,4]
__device__ float4 g_t2[N * 16];     // [N,64]
__device__ float4 g_agg2[N * 16];   // [N,64]
__device__ float  g_t3[N];
__device__ float  g_deg[N];
__device__ float  g_norm[E];
__device__ int    g_src[E];
__device__ int    g_dst[E];
__device__ int    g_is64;

__device__ __forceinline__ void red_add_v4(float* p, float4 v) {
    asm volatile("red.global.add.v4.f32 [%0], {%1,%2,%3,%4};"
                 :: "l"(p), "f"(v.x), "f"(v.y), "f"(v.z), "f"(v.w)
                 : "memory");
}
__device__ __forceinline__ float to_tf32(float v) {
    float r;
    asm("cvt.rna.tf32.f32 %0, %1;" : "=f"(r) : "f"(v));
    return r;
}
__device__ __forceinline__ void mma_tf32(
    float& c0, float& c1, float& c2, float& c3,
    unsigned a0, unsigned a1, unsigned a2, unsigned a3,
    unsigned b0, unsigned b1) {
    asm("mma.sync.aligned.m16n8k8.row.col.f32.tf32.tf32.f32 "
        "{%0,%1,%2,%3}, {%4,%5,%6,%7}, {%8,%9}, {%0,%1,%2,%3};"
        : "+f"(c0), "+f"(c1), "+f"(c2), "+f"(c3)
        : "r"(a0), "r"(a1), "r"(a2), "r"(a3), "r"(b0), "r"(b1));
}

// ---------------- kernels ----------------

// grid-wide: init deg=1 (self-loop) and agg1=0; block 0 sniffs edge dtype.
__global__ void k_detect_init(const int* __restrict__ ei32) {
    int i = blockIdx.x * blockDim.x + threadIdx.x;
    int stride = gridDim.x * blockDim.x;
    const float4 z4 = make_float4(0.f, 0.f, 0.f, 0.f);
    for (int j = i; j < N; j += stride) {
        g_deg[j] = 1.0f;
        g_agg1[j] = z4;
    }
    if (blockIdx.x == 0) {
        __shared__ unsigned s[256];
        unsigned acc = 0;
        for (int t = threadIdx.x; t < 8192; t += 256) acc |= (unsigned)ei32[2 * t + 1];
        s[threadIdx.x] = acc;
        __syncthreads();
        for (int o = 128; o; o >>= 1) {
            if (threadIdx.x < o) s[threadIdx.x] |= s[threadIdx.x + o];
            __syncthreads();
        }
        if (threadIdx.x == 0) g_is64 = (s[0] == 0) ? 1 : 0;
    }
}

__global__ void k_decode_deg(const int* __restrict__ ei32, const float* __restrict__ w) {
    int e = blockIdx.x * blockDim.x + threadIdx.x;
    if (e >= E) return;
    int s, d;
    if (g_is64) { s = ei32[2 * e]; d = ei32[2 * (E + e)]; }
    else        { s = ei32[e];     d = ei32[E + e]; }
    if ((unsigned)s >= (unsigned)N) s = 0;
    if ((unsigned)d >= (unsigned)N) d = 0;
    g_src[e] = s;
    g_dst[e] = d;
    atomicAdd(&g_deg[d], w[e]);
}

__global__ void k_norm_agg1(const float* __restrict__ x, const float* __restrict__ w) {
    int e = blockIdx.x * blockDim.x + threadIdx.x;
    if (e >= E) return;
    int s = g_src[e], d = g_dst[e];
    float nr = rsqrtf(g_deg[s]) * w[e] * rsqrtf(g_deg[d]);
    g_norm[e] = nr;
    float4 v = ((const float4*)x)[s];
    v.x *= nr; v.y *= nr; v.z *= nr; v.w *= nr;
    red_add_v4((float*)&g_agg1[d], v);
}

// fused l1 + gemm2 via 3xTF32 mma, 256 threads. Block computes h1 tile
// [128x128] hi/lo in smem, W2 hi/lo likewise; 8 warps each do one 16-row
// m-tile of [128x64] = h1 @ W2 (3 MMAs per tile). Also zeroes g_agg2 rows.
__global__ __launch_bounds__(256) void k_l1gemm2(
    const float* __restrict__ x, const float* __restrict__ W1,
    const float* __restrict__ b1, const float* __restrict__ W2) {
    extern __shared__ float smem[];
    float* h1h = smem;                     // [128][132] hi
    float* h1l = h1h + SM_H1;              // [128][132] lo
    float* w2h = h1l + SM_H1;              // [128][72]  hi
    float* w2l = w2h + SM_W2;              // [128][72]  lo
    float* w1s = w2l + SM_W2;              // [4][128]
    float* b1s = w1s + 512;                // [128]

    int t = threadIdx.x;
    for (int i = t; i < 128 * 64; i += 256) {
        int k = i >> 6, n = i & 63;
        float v = W2[i];
        float hi = to_tf32(v);
        w2h[k * W2_STRIDE + n] = hi;
        w2l[k * W2_STRIDE + n] = to_tf32(v - hi);
    }
    for (int i = t; i < 512; i += 256) w1s[i] = W1[i];
    if (t < 128) b1s[t] = b1[t];
    __syncthreads();   // <-- R15 fix: staging must complete before h1 compute reads w1s/b1s

    int node0 = blockIdx.x * TBN;

    // h1 compute: each thread does half a row (64 k-values).
    {
        int nl = t & 127;            // node within tile
        int half = t >> 7;           // 0 or 1
        int node = node0 + nl;
        float v0 = 0.f, v1 = 0.f, v2 = 0.f, v3 = 0.f;
        if (node < N) {
            if (half == 0) {
                const float4 z4 = make_float4(0.f, 0.f, 0.f, 0.f);
                float4* a2 = &g_agg2[node * 16];
#pragma unroll
                for (int c = 0; c < 16; c++) a2[c] = z4;
            }
            float4 ag = g_agg1[node];
            float4 xv = ((const float4*)x)[node];
            float s2 = 1.0f / g_deg[node];
            v0 = ag.x + s2 * xv.x;
            v1 = ag.y + s2 * xv.y;
            v2 = ag.z + s2 * xv.z;
            v3 = ag.w + s2 * xv.w;
        }
        float* hh = &h1h[nl * H1_STRIDE];
        float* hl = &h1l[nl * H1_STRIDE];
        int k4beg = half * 16, k4end = k4beg + 16;
        if (node < N) {
#pragma unroll 4
            for (int k4 = k4beg; k4 < k4end; k4++) {
                float4 r0 = ((const float4*)w1s)[k4];
                float4 r1 = ((const float4*)(w1s + 128))[k4];
                float4 r2 = ((const float4*)(w1s + 256))[k4];
                float4 r3 = ((const float4*)(w1s + 384))[k4];
                float4 bb = ((const float4*)b1s)[k4];
                float h0 = fmaxf(bb.x + v0 * r0.x + v1 * r1.x + v2 * r2.x + v3 * r3.x, 0.f);
                float h1v = fmaxf(bb.y + v0 * r0.y + v1 * r1.y + v2 * r2.y + v3 * r3.y, 0.f);
                float h2 = fmaxf(bb.z + v0 * r0.z + v1 * r1.z + v2 * r2.z + v3 * r3.z, 0.f);
                float h3 = fmaxf(bb.w + v0 * r0.w + v1 * r1.w + v2 * r2.w + v3 * r3.w, 0.f);
                float e0 = to_tf32(h0), e1 = to_tf32(h1v), e2 = to_tf32(h2), e3 = to_tf32(h3);
                hh[4 * k4 + 0] = e0; hl[4 * k4 + 0] = to_tf32(h0 - e0);
                hh[4 * k4 + 1] = e1; hl[4 * k4 + 1] = to_tf32(h1v - e1);
                hh[4 * k4 + 2] = e2; hl[4 * k4 + 2] = to_tf32(h2 - e2);
                hh[4 * k4 + 3] = e3; hl[4 * k4 + 3] = to_tf32(h3 - e3);
            }
        } else {
#pragma unroll 8
            for (int k = 4 * k4beg; k < 4 * k4end; k++) { hh[k] = 0.f; hl[k] = 0.f; }
        }
    }
    __syncthreads();

    // MMA: warp w handles one m-tile of 16 rows: [16 x 64]
    int w = t >> 5, lane = t & 31;
    int gid = lane >> 2, tig = lane & 3;
    int m0 = w * 16;

    float c[8][4];
#pragma unroll
    for (int nt = 0; nt < 8; nt++)
#pragma unroll
        for (int r = 0; r < 4; r++) c[nt][r] = 0.f;

#pragma unroll 1
    for (int kt = 0; kt < 16; kt++) {
        int k0 = kt * 8;
        int r0 = m0 + gid;
        int o00 = r0 * H1_STRIDE + k0 + tig;
        int o10 = (r0 + 8) * H1_STRIDE + k0 + tig;
        unsigned ah0 = __float_as_uint(h1h[o00]);
        unsigned ah1 = __float_as_uint(h1h[o10]);
        unsigned ah2 = __float_as_uint(h1h[o00 + 4]);
        unsigned ah3 = __float_as_uint(h1h[o10 + 4]);
        unsigned al0 = __float_as_uint(h1l[o00]);
        unsigned al1 = __float_as_uint(h1l[o10]);
        unsigned al2 = __float_as_uint(h1l[o00 + 4]);
        unsigned al3 = __float_as_uint(h1l[o10 + 4]);
#pragma unroll
        for (int nt = 0; nt < 8; nt++) {
            int n0 = nt * 8;
            int ob0 = (k0 + tig) * W2_STRIDE + n0 + gid;
            int ob1 = (k0 + tig + 4) * W2_STRIDE + n0 + gid;
            unsigned bh0 = __float_as_uint(w2h[ob0]);
            unsigned bh1 = __float_as_uint(w2h[ob1]);
            unsigned bl0 = __float_as_uint(w2l[ob0]);
            unsigned bl1 = __float_as_uint(w2l[ob1]);
            mma_tf32(c[nt][0], c[nt][1], c[nt][2], c[nt][3],
                     al0, al1, al2, al3, bh0, bh1);
            mma_tf32(c[nt][0], c[nt][1], c[nt][2], c[nt][3],
                     ah0, ah1, ah2, ah3, bl0, bl1);
            mma_tf32(c[nt][0], c[nt][1], c[nt][2], c[nt][3],
                     ah0, ah1, ah2, ah3, bh0, bh1);
        }
    }

    // store C -> g_t2
    float* t2f = (float*)g_t2;
    {
        int r0 = node0 + m0 + gid;
        int r1 = r0 + 8;
#pragma unroll
        for (int nt = 0; nt < 8; nt++) {
            int col = nt * 8 + tig * 2;
            if (r0 < N)
                *(float2*)(t2f + r0 * 64 + col) = make_float2(c[nt][0], c[nt][1]);
            if (r1 < N)
                *(float2*)(t2f + r1 * 64 + col) = make_float2(c[nt][2], c[nt][3]);
        }
    }
}

// layer-2 aggregation in dim 64: 16 threads (float4 chunks) per edge
__global__ void k_agg2() {
    int idx = blockIdx.x * blockDim.x + threadIdx.x;
    if (idx >= E * 16) return;
    int e = idx >> 4, c = idx & 15;
    int s = g_src[e], d = g_dst[e];
    float nr = g_norm[e];
    float4 v = g_t2[s * 16 + c];
    v.x *= nr; v.y *= nr; v.z *= nr; v.w *= nr;
    red_add_v4((float*)&g_agg2[d * 16 + c], v);
}

// fused: h2 = relu(agg2 + dis2*t2 + b2); t3 = h2 . W3; out = dis2*t3 + b3
__global__ void k_l2gemm3(const float* __restrict__ b2, const float* __restrict__ W3,
                          const float* __restrict__ b3, float* __restrict__ out) {
    __shared__ float sw[64];
    __shared__ float sb2[64];
    if (threadIdx.x < 64) { sw[threadIdx.x] = W3[threadIdx.x]; sb2[threadIdx.x] = b2[threadIdx.x]; }
    __syncthreads();
    int gw = (blockIdx.x * blockDim.x + threadIdx.x) >> 5;
    int lane = threadIdx.x & 31;
    if (gw >= N) return;
    float s2 = 1.0f / g_deg[gw];
    float2 a = ((const float2*)((const float*)g_agg2 + gw * 64))[lane];
    float2 t = ((const float2*)((const float*)g_t2   + gw * 64))[lane];
    float h0 = fmaxf(a.x + s2 * t.x + sb2[2 * lane],     0.f);
    float h1 = fmaxf(a.y + s2 * t.y + sb2[2 * lane + 1], 0.f);
    float p = h0 * sw[2 * lane] + h1 * sw[2 * lane + 1];
#pragma unroll
    for (int off = 16; off; off >>= 1) p += __shfl_down_sync(0xffffffffu, p, off);
    if (lane == 0) {
        g_t3[gw] = p;
        out[gw] = s2 * p + b3[0];   // self-loop + bias; edge atomics add on top
    }
}

// layer-3 aggregation (scalar atomics into out)
__global__ void k_agg3(float* __restrict__ out) {
    int e = blockIdx.x * blockDim.x + threadIdx.x;
    if (e >= E) return;
    atomicAdd(&out[g_dst[e]], g_norm[e] * g_t3[g_src[e]]);
}

// ---------------- launch ----------------
extern "C" void kernel_launch(void* const* d_in, const int* in_sizes, int n_in,
                              void* d_out, int out_size) {
    const float* x  = (const float*)d_in[0];
    const int*   ei = (const int*)d_in[1];      // dtype sniffed on device
    const float* w  = (const float*)d_in[2];
    const float* W1 = (const float*)d_in[3];
    const float* b1 = (const float*)d_in[4];
    const float* W2 = (const float*)d_in[5];
    const float* b2 = (const float*)d_in[6];
    const float* W3 = (const float*)d_in[7];
    const float* b3 = (const float*)d_in[8];
    float* out = (float*)d_out;

    const int B = 256;

    cudaFuncSetAttribute(k_l1gemm2, cudaFuncAttributeMaxDynamicSharedMemorySize, SMEM_BYTES);

    k_detect_init<<<(N + B - 1) / B, B>>>(ei);
    k_decode_deg<<<(E + B - 1) / B, B>>>(ei, w);
    k_norm_agg1<<<(E + B - 1) / B, B>>>(x, w);
    k_l1gemm2<<<(N + TBN - 1) / TBN, 256, SMEM_BYTES>>>(x, W1, b1, W2);
    k_agg2<<<(E * 16 + B - 1) / B, B>>>();
    k_l2gemm3<<<(N * 32 + B - 1) / B, B>>>(b2, W3, b3, out);
    k_agg3<<<(E + B - 1) / B, B>>>(out);
}

// round 17
// speedup vs baseline: 1.1029x; 1.0240x over previous
#include <cuda_runtime.h>
#include <cuda_bf16.h>

// GCN 3-layer, N=100000, E=800000. Aggregate in the smaller dim per layer.
// R16: GEMM mainloop was serial LDS->MMA chains (regs=52 — ptxas batched
//      nothing; 29-cyc smem latency exposed per nt step, 2 warps/SMSP can't
//      hide it). Restructure each kt iteration: batch-load ALL fragments
//      (8 A + 32 B words, MLP~40) into register arrays, then burst 24 MMAs.
//      Identical indexing/layout to the passing R15; only load scheduling.

static constexpr int N = 100000;
static constexpr int E = 800000;

static constexpr int TBN = 128;          // nodes per block
static constexpr int H1_STRIDE = 132;    // conflict-free A-frag loads
static constexpr int W2_STRIDE = 72;     // conflict-free B-frag loads
static constexpr int SM_H1 = TBN * H1_STRIDE;          // 16896 floats
static constexpr int SM_W2 = 128 * W2_STRIDE;          // 9216 floats
static constexpr int SMEM_FLOATS = 2 * SM_H1 + 2 * SM_W2 + 512 + 128;
static constexpr int SMEM_BYTES = SMEM_FLOATS * 4;     // 211,456 bytes

__device__ float4 g_agg1[N];        // [N,4]
__device__ float4 g_t2[N * 16];     // [N,64]
__device__ float4 g_agg2[N * 16];   // [N,64]
__device__ float  g_t3[N];
__device__ float  g_deg[N];
__device__ float  g_norm[E];
__device__ int    g_src[E];
__device__ int    g_dst[E];
__device__ int    g_is64;

__device__ __forceinline__ void red_add_v4(float* p, float4 v) {
    asm volatile("red.global.add.v4.f32 [%0], {%1,%2,%3,%4};"
                 :: "l"(p), "f"(v.x), "f"(v.y), "f"(v.z), "f"(v.w)
                 : "memory");
}
__device__ __forceinline__ float to_tf32(float v) {
    float r;
    asm("cvt.rna.tf32.f32 %0, %1;" : "=f"(r) : "f"(v));
    return r;
}
__device__ __forceinline__ void mma_tf32(
    float& c0, float& c1, float& c2, float& c3,
    unsigned a0, unsigned a1, unsigned a2, unsigned a3,
    unsigned b0, unsigned b1) {
    asm("mma.sync.aligned.m16n8k8.row.col.f32.tf32.tf32.f32 "
        "{%0,%1,%2,%3}, {%4,%5,%6,%7}, {%8,%9}, {%0,%1,%2,%3};"
        : "+f"(c0), "+f"(c1), "+f"(c2), "+f"(c3)
        : "r"(a0), "r"(a1), "r"(a2), "r"(a3), "r"(b0), "r"(b1));
}

// ---------------- kernels ----------------

// grid-wide: init deg=1 (self-loop) and agg1=0; block 0 sniffs edge dtype.
__global__ void k_detect_init(const int* __restrict__ ei32) {
    int i = blockIdx.x * blockDim.x + threadIdx.x;
    int stride = gridDim.x * blockDim.x;
    const float4 z4 = make_float4(0.f, 0.f, 0.f, 0.f);
    for (int j = i; j < N; j += stride) {
        g_deg[j] = 1.0f;
        g_agg1[j] = z4;
    }
    if (blockIdx.x == 0) {
        __shared__ unsigned s[256];
        unsigned acc = 0;
        for (int t = threadIdx.x; t < 8192; t += 256) acc |= (unsigned)ei32[2 * t + 1];
        s[threadIdx.x] = acc;
        __syncthreads();
        for (int o = 128; o; o >>= 1) {
            if (threadIdx.x < o) s[threadIdx.x] |= s[threadIdx.x + o];
            __syncthreads();
        }
        if (threadIdx.x == 0) g_is64 = (s[0] == 0) ? 1 : 0;
    }
}

__global__ void k_decode_deg(const int* __restrict__ ei32, const float* __restrict__ w) {
    int e = blockIdx.x * blockDim.x + threadIdx.x;
    if (e >= E) return;
    int s, d;
    if (g_is64) { s = ei32[2 * e]; d = ei32[2 * (E + e)]; }
    else        { s = ei32[e];     d = ei32[E + e]; }
    if ((unsigned)s >= (unsigned)N) s = 0;
    if ((unsigned)d >= (unsigned)N) d = 0;
    g_src[e] = s;
    g_dst[e] = d;
    atomicAdd(&g_deg[d], w[e]);
}

__global__ void k_norm_agg1(const float* __restrict__ x, const float* __restrict__ w) {
    int e = blockIdx.x * blockDim.x + threadIdx.x;
    if (e >= E) return;
    int s = g_src[e], d = g_dst[e];
    float nr = rsqrtf(g_deg[s]) * w[e] * rsqrtf(g_deg[d]);
    g_norm[e] = nr;
    float4 v = ((const float4*)x)[s];
    v.x *= nr; v.y *= nr; v.z *= nr; v.w *= nr;
    red_add_v4((float*)&g_agg1[d], v);
}

// fused l1 + gemm2 via 3xTF32 mma, 256 threads, batched fragment loads.
__global__ __launch_bounds__(256) void k_l1gemm2(
    const float* __restrict__ x, const float* __restrict__ W1,
    const float* __restrict__ b1, const float* __restrict__ W2) {
    extern __shared__ float smem[];
    float* h1h = smem;                     // [128][132] hi
    float* h1l = h1h + SM_H1;              // [128][132] lo
    float* w2h = h1l + SM_H1;              // [128][72]  hi
    float* w2l = w2h + SM_W2;              // [128][72]  lo
    float* w1s = w2l + SM_W2;              // [4][128]
    float* b1s = w1s + 512;                // [128]

    int t = threadIdx.x;
    for (int i = t; i < 128 * 64; i += 256) {
        int k = i >> 6, n = i & 63;
        float v = W2[i];
        float hi = to_tf32(v);
        w2h[k * W2_STRIDE + n] = hi;
        w2l[k * W2_STRIDE + n] = to_tf32(v - hi);
    }
    for (int i = t; i < 512; i += 256) w1s[i] = W1[i];
    if (t < 128) b1s[t] = b1[t];
    __syncthreads();   // staging complete before h1 compute reads w1s/b1s

    int node0 = blockIdx.x * TBN;

    // h1 compute: each thread does half a row (64 k-values).
    {
        int nl = t & 127;            // node within tile
        int half = t >> 7;           // 0 or 1
        int node = node0 + nl;
        float v0 = 0.f, v1 = 0.f, v2 = 0.f, v3 = 0.f;
        if (node < N) {
            if (half == 0) {
                const float4 z4 = make_float4(0.f, 0.f, 0.f, 0.f);
                float4* a2 = &g_agg2[node * 16];
#pragma unroll
                for (int c = 0; c < 16; c++) a2[c] = z4;
            }
            float4 ag = g_agg1[node];
            float4 xv = ((const float4*)x)[node];
            float s2 = 1.0f / g_deg[node];
            v0 = ag.x + s2 * xv.x;
            v1 = ag.y + s2 * xv.y;
            v2 = ag.z + s2 * xv.z;
            v3 = ag.w + s2 * xv.w;
        }
        float* hh = &h1h[nl * H1_STRIDE];
        float* hl = &h1l[nl * H1_STRIDE];
        int k4beg = half * 16, k4end = k4beg + 16;
        if (node < N) {
#pragma unroll 4
            for (int k4 = k4beg; k4 < k4end; k4++) {
                float4 r0 = ((const float4*)w1s)[k4];
                float4 r1 = ((const float4*)(w1s + 128))[k4];
                float4 r2 = ((const float4*)(w1s + 256))[k4];
                float4 r3 = ((const float4*)(w1s + 384))[k4];
                float4 bb = ((const float4*)b1s)[k4];
                float h0 = fmaxf(bb.x + v0 * r0.x + v1 * r1.x + v2 * r2.x + v3 * r3.x, 0.f);
                float h1v = fmaxf(bb.y + v0 * r0.y + v1 * r1.y + v2 * r2.y + v3 * r3.y, 0.f);
                float h2 = fmaxf(bb.z + v0 * r0.z + v1 * r1.z + v2 * r2.z + v3 * r3.z, 0.f);
                float h3 = fmaxf(bb.w + v0 * r0.w + v1 * r1.w + v2 * r2.w + v3 * r3.w, 0.f);
                float e0 = to_tf32(h0), e1 = to_tf32(h1v), e2 = to_tf32(h2), e3 = to_tf32(h3);
                hh[4 * k4 + 0] = e0; hl[4 * k4 + 0] = to_tf32(h0 - e0);
                hh[4 * k4 + 1] = e1; hl[4 * k4 + 1] = to_tf32(h1v - e1);
                hh[4 * k4 + 2] = e2; hl[4 * k4 + 2] = to_tf32(h2 - e2);
                hh[4 * k4 + 3] = e3; hl[4 * k4 + 3] = to_tf32(h3 - e3);
            }
        } else {
#pragma unroll 8
            for (int k = 4 * k4beg; k < 4 * k4end; k++) { hh[k] = 0.f; hl[k] = 0.f; }
        }
    }
    __syncthreads();

    // MMA: warp w handles one m-tile of 16 rows: [16 x 64]
    int w = t >> 5, lane = t & 31;
    int gid = lane >> 2, tig = lane & 3;
    int m0 = w * 16;

    float c[8][4];
#pragma unroll
    for (int nt = 0; nt < 8; nt++)
#pragma unroll
        for (int r = 0; r < 4; r++) c[nt][r] = 0.f;

#pragma unroll 1
    for (int kt = 0; kt < 16; kt++) {
        int k0 = kt * 8;

        // ---- batch-load ALL fragments for this kt (MLP ~40) ----
        int r0 = m0 + gid;
        int o00 = r0 * H1_STRIDE + k0 + tig;
        int o10 = (r0 + 8) * H1_STRIDE + k0 + tig;
        unsigned ah0 = __float_as_uint(h1h[o00]);
        unsigned ah1 = __float_as_uint(h1h[o10]);
        unsigned ah2 = __float_as_uint(h1h[o00 + 4]);
        unsigned ah3 = __float_as_uint(h1h[o10 + 4]);
        unsigned al0 = __float_as_uint(h1l[o00]);
        unsigned al1 = __float_as_uint(h1l[o10]);
        unsigned al2 = __float_as_uint(h1l[o00 + 4]);
        unsigned al3 = __float_as_uint(h1l[o10 + 4]);

        unsigned bh[8][2], bl[8][2];
        int obA = (k0 + tig) * W2_STRIDE + gid;
        int obB = (k0 + tig + 4) * W2_STRIDE + gid;
#pragma unroll
        for (int nt = 0; nt < 8; nt++) {
            bh[nt][0] = __float_as_uint(w2h[obA + nt * 8]);
            bh[nt][1] = __float_as_uint(w2h[obB + nt * 8]);
        }
#pragma unroll
        for (int nt = 0; nt < 8; nt++) {
            bl[nt][0] = __float_as_uint(w2l[obA + nt * 8]);
            bl[nt][1] = __float_as_uint(w2l[obB + nt * 8]);
        }

        // ---- MMA burst: 24 tensor ops, 8 independent accumulator chains ----
#pragma unroll
        for (int nt = 0; nt < 8; nt++)
            mma_tf32(c[nt][0], c[nt][1], c[nt][2], c[nt][3],
                     al0, al1, al2, al3, bh[nt][0], bh[nt][1]);
#pragma unroll
        for (int nt = 0; nt < 8; nt++)
            mma_tf32(c[nt][0], c[nt][1], c[nt][2], c[nt][3],
                     ah0, ah1, ah2, ah3, bl[nt][0], bl[nt][1]);
#pragma unroll
        for (int nt = 0; nt < 8; nt++)
            mma_tf32(c[nt][0], c[nt][1], c[nt][2], c[nt][3],
                     ah0, ah1, ah2, ah3, bh[nt][0], bh[nt][1]);
    }

    // store C -> g_t2
    float* t2f = (float*)g_t2;
    {
        int r0 = node0 + m0 + gid;
        int r1 = r0 + 8;
#pragma unroll
        for (int nt = 0; nt < 8; nt++) {
            int col = nt * 8 + tig * 2;
            if (r0 < N)
                *(float2*)(t2f + r0 * 64 + col) = make_float2(c[nt][0], c[nt][1]);
            if (r1 < N)
                *(float2*)(t2f + r1 * 64 + col) = make_float2(c[nt][2], c[nt][3]);
        }
    }
}

// layer-2 aggregation in dim 64: 16 threads (float4 chunks) per edge
__global__ void k_agg2() {
    int idx = blockIdx.x * blockDim.x + threadIdx.x;
    if (idx >= E * 16) return;
    int e = idx >> 4, c = idx & 15;
    int s = g_src[e], d = g_dst[e];
    float nr = g_norm[e];
    float4 v = g_t2[s * 16 + c];
    v.x *= nr; v.y *= nr; v.z *= nr; v.w *= nr;
    red_add_v4((float*)&g_agg2[d * 16 + c], v);
}

// fused: h2 = relu(agg2 + dis2*t2 + b2); t3 = h2 . W3; out = dis2*t3 + b3
__global__ void k_l2gemm3(const float* __restrict__ b2, const float* __restrict__ W3,
                          const float* __restrict__ b3, float* __restrict__ out) {
    __shared__ float sw[64];
    __shared__ float sb2[64];
    if (threadIdx.x < 64) { sw[threadIdx.x] = W3[threadIdx.x]; sb2[threadIdx.x] = b2[threadIdx.x]; }
    __syncthreads();
    int gw = (blockIdx.x * blockDim.x + threadIdx.x) >> 5;
    int lane = threadIdx.x & 31;
    if (gw >= N) return;
    float s2 = 1.0f / g_deg[gw];
    float2 a = ((const float2*)((const float*)g_agg2 + gw * 64))[lane];
    float2 t = ((const float2*)((const float*)g_t2   + gw * 64))[lane];
    float h0 = fmaxf(a.x + s2 * t.x + sb2[2 * lane],     0.f);
    float h1 = fmaxf(a.y + s2 * t.y + sb2[2 * lane + 1], 0.f);
    float p = h0 * sw[2 * lane] + h1 * sw[2 * lane + 1];
#pragma unroll
    for (int off = 16; off; off >>= 1) p += __shfl_down_sync(0xffffffffu, p, off);
    if (lane == 0) {
        g_t3[gw] = p;
        out[gw] = s2 * p + b3[0];   // self-loop + bias; edge atomics add on top
    }
}

// layer-3 aggregation (scalar atomics into out)
__global__ void k_agg3(float* __restrict__ out) {
    int e = blockIdx.x * blockDim.x + threadIdx.x;
    if (e >= E) return;
    atomicAdd(&out[g_dst[e]], g_norm[e] * g_t3[g_src[e]]);
}

// ---------------- launch ----------------
extern "C" void kernel_launch(void* const* d_in, const int* in_sizes, int n_in,
                              void* d_out, int out_size) {
    const float* x  = (const float*)d_in[0];
    const int*   ei = (const int*)d_in[1];      // dtype sniffed on device
    const float* w  = (const float*)d_in[2];
    const float* W1 = (const float*)d_in[3];
    const float* b1 = (const float*)d_in[4];
    const float* W2 = (const float*)d_in[5];
    const float* b2 = (const float*)d_in[6];
    const float* W3 = (const float*)d_in[7];
    const float* b3 = (const float*)d_in[8];
    float* out = (float*)d_out;

    const int B = 256;

    cudaFuncSetAttribute(k_l1gemm2, cudaFuncAttributeMaxDynamicSharedMemorySize, SMEM_BYTES);

    k_detect_init<<<(N + B - 1) / B, B>>>(ei);
    k_decode_deg<<<(E + B - 1) / B, B>>>(ei, w);
    k_norm_agg1<<<(E + B - 1) / B, B>>>(x, w);
    k_l1gemm2<<<(N + TBN - 1) / TBN, 256, SMEM_BYTES>>>(x, W1, b1, W2);
    k_agg2<<<(E * 16 + B - 1) / B, B>>>();
    k_l2gemm3<<<(N * 32 + B - 1) / B, B>>>(b2, W3, b3, out);
    k_agg3<<<(E + B - 1) / B, B>>>(out);
}